// round 3
// baseline (speedup 1.0000x reference)
#include <cuda_runtime.h>
#include <cuda_bf16.h>
#include <cstdint>

#define MAX_N 100000
#define MAX_E 1250000
#define D 64
#define SCAN_BLK 2048
#define MAX_SCAN_BLKS 64
#define TN 64                      // nodes per transform block
#define XFORM_SMEM_FLOATS (4096 + 4096 + 8192 + 8192 + 64)
#define XFORM_SMEM_BYTES (XFORM_SMEM_FLOATS * 4)

// Scratch (device globals; no allocation allowed).
__device__ float g_mean[MAX_N * D];
__device__ float g_h[MAX_N * D];
__device__ int   g_cnt[MAX_N];
__device__ int   g_off[MAX_N];
__device__ int   g_pos[MAX_N];
__device__ int   g_csr[MAX_E];
__device__ int   g_blk[MAX_SCAN_BLKS];

// ---------------------------------------------------------------------------
__global__ void zero_int_kernel(int* __restrict__ p, int n) {
    int i = blockIdx.x * blockDim.x + threadIdx.x;
    if (i < n) p[i] = 0;
}

__global__ void hist_kernel(const int* __restrict__ ei, int* __restrict__ cnt, int E) {
    int e = blockIdx.x * blockDim.x + threadIdx.x;
    if (e < E) atomicAdd(&cnt[ei[E + e]], 1);
}

__global__ __launch_bounds__(256)
void scan_k1(const int* __restrict__ cnt, int* __restrict__ off,
             int* __restrict__ blk, int n) {
    __shared__ int warp_excl[8];
    int t = threadIdx.x;
    int lane = t & 31, w = t >> 5;
    int base = blockIdx.x * SCAN_BLK + t * 8;
    int v[8];
    int s = 0;
#pragma unroll
    for (int q = 0; q < 8; q++) {
        int idx = base + q;
        v[q] = (idx < n) ? cnt[idx] : 0;
        s += v[q];
    }
    int ps = s;
#pragma unroll
    for (int d = 1; d < 32; d <<= 1) {
        int o = __shfl_up_sync(0xffffffffu, ps, d);
        if (lane >= d) ps += o;
    }
    if (lane == 31) warp_excl[w] = ps;
    __syncthreads();
    if (w == 0 && lane < 8) {
        int ws = warp_excl[lane];
        int pw = ws;
#pragma unroll
        for (int d = 1; d < 8; d <<= 1) {
            int o = __shfl_up_sync(0xffu, pw, d);
            if (lane >= d) pw += o;
        }
        warp_excl[lane] = pw - ws;
    }
    __syncthreads();
    int excl = warp_excl[w] + (ps - s);
    int run = excl;
#pragma unroll
    for (int q = 0; q < 8; q++) {
        int idx = base + q;
        if (idx < n) off[idx] = run;
        run += v[q];
    }
    if (t == 255) blk[blockIdx.x] = excl + s;
}

__global__ void scan_k2(int* __restrict__ blk, int nb) {
    __shared__ int sm[MAX_SCAN_BLKS];
    int t = threadIdx.x;
    int v = (t < nb) ? blk[t] : 0;
    sm[t] = v;
    __syncthreads();
    for (int d = 1; d < MAX_SCAN_BLKS; d <<= 1) {
        int o = (t >= d) ? sm[t - d] : 0;
        __syncthreads();
        sm[t] += o;
        __syncthreads();
    }
    if (t < nb) blk[t] = sm[t] - v;
}

__global__ void scan_k3(int* __restrict__ off, const int* __restrict__ blk,
                        int* __restrict__ pos, int n) {
    int i = blockIdx.x * blockDim.x + threadIdx.x;
    if (i < n) {
        int o = off[i] + blk[i >> 11];
        off[i] = o;
        pos[i] = o;
    }
}

__global__ void fill_kernel(const int* __restrict__ ei, int* __restrict__ pos,
                            int* __restrict__ csr, int E) {
    int e = blockIdx.x * blockDim.x + threadIdx.x;
    if (e < E) {
        int dst = ei[E + e];
        int p = atomicAdd(&pos[dst], 1);
        csr[p] = ei[e];
    }
}

// ---------------------------------------------------------------------------
// Aggregate: mean[node] = (1/max(cnt,1)) * sum_{i in CSR[node]} x[csr[i]]
// 16 threads per node, each owns one float4 chunk. No atomics.
// ---------------------------------------------------------------------------
__global__ __launch_bounds__(256)
void aggregate_kernel(const float4* __restrict__ x4,
                      const int* __restrict__ off,
                      const int* __restrict__ cnt,
                      const int* __restrict__ csr,
                      float4* __restrict__ mean4, int n) {
    int tid = blockIdx.x * blockDim.x + threadIdx.x;
    int node = tid >> 4;
    if (node >= n) return;
    int j = tid & 15;
    int s = off[node];
    int c = cnt[node];
    int e = s + c;

    float4 a0 = make_float4(0.f, 0.f, 0.f, 0.f);
    float4 a1 = make_float4(0.f, 0.f, 0.f, 0.f);
    int i = s;
    for (; i + 2 <= e; i += 2) {
        int s0 = csr[i];
        int s1 = csr[i + 1];
        float4 v0 = x4[s0 * 16 + j];
        float4 v1 = x4[s1 * 16 + j];
        a0.x += v0.x; a0.y += v0.y; a0.z += v0.z; a0.w += v0.w;
        a1.x += v1.x; a1.y += v1.y; a1.z += v1.z; a1.w += v1.w;
    }
    if (i < e) {
        float4 v = x4[csr[i] * 16 + j];
        a0.x += v.x; a0.y += v.y; a0.z += v.z; a0.w += v.w;
    }
    float inv = 1.0f / fmaxf((float)c, 1.0f);
    a0.x = (a0.x + a1.x) * inv;
    a0.y = (a0.y + a1.y) * inv;
    a0.z = (a0.z + a1.z) * inv;
    a0.w = (a0.w + a1.w) * inv;
    mean4[node * 16 + j] = a0;
}

// ---------------------------------------------------------------------------
// Packed f32x2 FMA (FFMA2): d = a * b + d, elementwise on packed pairs.
// ---------------------------------------------------------------------------
__device__ __forceinline__ void fma2(uint64_t& d, uint64_t a, uint64_t b) {
    asm("fma.rn.f32x2 %0, %1, %2, %0;" : "+l"(d) : "l"(a), "l"(b));
}

// ---------------------------------------------------------------------------
// Transform: out[i] = act( mean[i] @ W_l + b_l + xin[i] @ W_r )
// 64 nodes/block, 128 threads. Thread = 8 nodes x 4 cols, all FMA2.
// Node values staged DUPLICATED ([k][2*node] = [k][2*node+1] = v) so the
// broadcast operand of fma.rn.f32x2 is a free register pair from LDS.128.
// Weight pairs (w[c],w[c+1]) are free register pairs from row-major LDS.128.
// Dynamic smem: sWl 16K | sWr 16K | sMd 32K | sXd 32K | sB 256B = 96.25KB.
// ---------------------------------------------------------------------------
__global__ __launch_bounds__(128)
void transform_kernel(const float* __restrict__ xin,
                      const float* __restrict__ mean,
                      const float* __restrict__ Wl,
                      const float* __restrict__ bl,
                      const float* __restrict__ Wr,
                      float* __restrict__ out,
                      int n, int do_relu) {
    extern __shared__ float smem[];
    float* sWl = smem;              // 4096
    float* sWr = smem + 4096;       // 4096
    float* sMd = smem + 8192;       // 64 * 128
    float* sXd = smem + 16384;      // 64 * 128
    float* sB  = smem + 24576;      // 64

    int t = threadIdx.x;
    for (int i = t; i < 1024; i += 128) {
        ((float4*)sWl)[i] = ((const float4*)Wl)[i];
        ((float4*)sWr)[i] = ((const float4*)Wr)[i];
    }
    if (t < D) sB[t] = bl[t];

    int base = blockIdx.x * TN;
    // Stage 64 nodes x 16 float4 chunks, transposed + duplicated.
    for (int i = t; i < TN * 16; i += 128) {
        int local = i & (TN - 1);
        int j = i >> 6;                 // chunk: k = 4j..4j+3
        int node = base + local;
        float4 mv, xv;
        if (node < n) {
            mv = ((const float4*)mean)[node * 16 + j];
            xv = ((const float4*)xin)[node * 16 + j];
        } else {
            mv = make_float4(0.f, 0.f, 0.f, 0.f);
            xv = mv;
        }
        int col = 2 * local;
#pragma unroll
        for (int q = 0; q < 4; q++) {
            float m = (q == 0) ? mv.x : (q == 1) ? mv.y : (q == 2) ? mv.z : mv.w;
            float xs = (q == 0) ? xv.x : (q == 1) ? xv.y : (q == 2) ? xv.z : xv.w;
            int row = (4 * j + q) * 2 * TN;
            sMd[row + col] = m;  sMd[row + col + 1] = m;
            sXd[row + col] = xs; sXd[row + col + 1] = xs;
        }
    }
    __syncthreads();

    int cg = t & 15;         // column group: cols 4*cg .. 4*cg+3
    int ng = t >> 4;         // node group 0..7: nodes ng*8 .. ng*8+7
    int c0 = cg * 4;
    int nb2 = ng * 16;       // duplicated-index base

    uint64_t b01 = *(const uint64_t*)&sB[c0];
    uint64_t b23 = *(const uint64_t*)&sB[c0 + 2];
    uint64_t acc[16];        // acc[2q] = cols(c0,c0+1), acc[2q+1] = cols(c0+2,c0+3)
#pragma unroll
    for (int q = 0; q < 8; q++) { acc[2 * q] = b01; acc[2 * q + 1] = b23; }

#pragma unroll
    for (int k = 0; k < D; k++) {
        ulonglong2 wl = *(const ulonglong2*)&sWl[k * D + c0];   // (wc0,wc1),(wc2,wc3)
        ulonglong2 wr = *(const ulonglong2*)&sWr[k * D + c0];
        const ulonglong2* md = (const ulonglong2*)&sMd[k * 2 * TN + nb2];
        const ulonglong2* xd = (const ulonglong2*)&sXd[k * 2 * TN + nb2];
#pragma unroll
        for (int h = 0; h < 4; h++) {       // 2 nodes per iteration
            ulonglong2 m2 = md[h];          // (m_{2h},m_{2h}), (m_{2h+1},m_{2h+1})
            ulonglong2 x2 = xd[h];
            int q0 = 2 * h, q1 = 2 * h + 1;
            fma2(acc[2 * q0],     m2.x, wl.x);
            fma2(acc[2 * q0 + 1], m2.x, wl.y);
            fma2(acc[2 * q1],     m2.y, wl.x);
            fma2(acc[2 * q1 + 1], m2.y, wl.y);
            fma2(acc[2 * q0],     x2.x, wr.x);
            fma2(acc[2 * q0 + 1], x2.x, wr.y);
            fma2(acc[2 * q1],     x2.y, wr.x);
            fma2(acc[2 * q1 + 1], x2.y, wr.y);
        }
    }

#pragma unroll
    for (int q = 0; q < 8; q++) {
        int node = base + ng * 8 + q;
        if (node >= n) continue;
        float2 lo = *(float2*)&acc[2 * q];
        float2 hi = *(float2*)&acc[2 * q + 1];
        float4 r = make_float4(lo.x, lo.y, hi.x, hi.y);
        if (do_relu) {
            r.x = fmaxf(r.x, 0.f); r.y = fmaxf(r.y, 0.f);
            r.z = fmaxf(r.z, 0.f); r.w = fmaxf(r.w, 0.f);
        }
        *(float4*)&out[node * D + c0] = r;
    }
}

// ---------------------------------------------------------------------------
extern "C" void kernel_launch(void* const* d_in, const int* in_sizes, int n_in,
                              void* d_out, int out_size) {
    const float* x   = (const float*)d_in[0];
    const int*   ei  = (const int*)d_in[1];
    const float* Wl1 = (const float*)d_in[2];
    const float* bl1 = (const float*)d_in[3];
    const float* Wr1 = (const float*)d_in[4];
    const float* Wl2 = (const float*)d_in[5];
    const float* bl2 = (const float*)d_in[6];
    const float* Wr2 = (const float*)d_in[7];
    float* out = (float*)d_out;

    int N = in_sizes[0] / D;   // 100000
    int E = in_sizes[1] / 2;   // 1250000

    float *mean, *h;
    int *cnt, *off, *pos, *csr, *blk;
    cudaGetSymbolAddress((void**)&mean, g_mean);
    cudaGetSymbolAddress((void**)&h,    g_h);
    cudaGetSymbolAddress((void**)&cnt,  g_cnt);
    cudaGetSymbolAddress((void**)&off,  g_off);
    cudaGetSymbolAddress((void**)&pos,  g_pos);
    cudaGetSymbolAddress((void**)&csr,  g_csr);
    cudaGetSymbolAddress((void**)&blk,  g_blk);

    static bool attr_set = false;
    if (!attr_set) {
        cudaFuncSetAttribute(transform_kernel,
                             cudaFuncAttributeMaxDynamicSharedMemorySize,
                             XFORM_SMEM_BYTES);
        attr_set = true;
    }

    int nb_scan = (N + SCAN_BLK - 1) / SCAN_BLK;

    // ---- CSR build (once; reused by both layers) ----
    zero_int_kernel<<<(N + 255) / 256, 256>>>(cnt, N);
    hist_kernel<<<(E + 255) / 256, 256>>>(ei, cnt, E);
    scan_k1<<<nb_scan, 256>>>(cnt, off, blk, N);
    scan_k2<<<1, MAX_SCAN_BLKS>>>(blk, nb_scan);
    scan_k3<<<(N + 255) / 256, 256>>>(off, blk, pos, N);
    fill_kernel<<<(E + 255) / 256, 256>>>(ei, pos, csr, E);

    int ab = (N * 16 + 255) / 256;
    int tb = (N + TN - 1) / TN;

    // ---- Layer 1 ----
    aggregate_kernel<<<ab, 256>>>((const float4*)x, off, cnt, csr,
                                  (float4*)mean, N);
    transform_kernel<<<tb, 128, XFORM_SMEM_BYTES>>>(x, mean, Wl1, bl1, Wr1, h, N, 1);

    // ---- Layer 2 ----
    aggregate_kernel<<<ab, 256>>>((const float4*)h, off, cnt, csr,
                                  (float4*)mean, N);
    transform_kernel<<<tb, 128, XFORM_SMEM_BYTES>>>(h, mean, Wl2, bl2, Wr2, out, N, 0);
}